// round 6
// baseline (speedup 1.0000x reference)
#include <cuda_runtime.h>
#include <stdint.h>

// ---------------------------------------------------------------------------
// SSIM loss, (16,3,512,512) fp32. Separable 11x11 Gaussian.
// Phase A: VERTICAL conv first, registers, straight from global (coalesced),
//          42 cols x 54 rows of v-results -> smem (only intermediate).
// Phase B: horizontal conv + SSIM from smem, LDS.128 conflict-free.
// 4 channels packed in ulonglong2: (mu1,mu2)|(Ess,E12) via fma.rn.f32x2.
// Single kernel; order-independent fixed-point atomic reduction.
// ---------------------------------------------------------------------------

#define IMG_H   512
#define IMG_W   512
#define PLANES  48
#define TX      32
#define TY      54
#define RSTRIP  9             // v-conv output rows per Phase-A thread
#define NSTRIPS 6             // 6*9 = 54
#define VCOLS   42            // TX + 10 columns of v-results
#define SVW     43            // ulonglong2 row stride (42 + 1 pad)
#define NT      256
#define NTILES_X 16
#define NTILES_Y 10           // 10*54 = 540 >= 512 (last tile predicated)
#define NBLOCKS (NTILES_X * NTILES_Y * PLANES)   // 7680
#define NPIX    12582912.0
#define FXSCALE 2147483648.0

__device__ __constant__ const float W11_c[11] = {
    0.00102838f, 0.00759876f, 0.03600077f, 0.10936071f, 0.21300554f,
    0.26601172f,
    0.21300554f, 0.10936071f, 0.03600077f, 0.00759876f, 0.00102838f
};

__device__ unsigned long long g_acc;   // zero at load; finalizer resets
__device__ unsigned int       g_cnt;

__device__ __forceinline__ unsigned long long pack2(float lo, float hi) {
    unsigned long long r;
    asm("mov.b64 %0, {%1, %2};" : "=l"(r) : "f"(lo), "f"(hi));
    return r;
}
__device__ __forceinline__ void unpack2(unsigned long long v, float &lo, float &hi) {
    asm("mov.b64 {%0, %1}, %2;" : "=f"(lo), "=f"(hi) : "l"(v));
}
__device__ __forceinline__ unsigned long long fma2(unsigned long long a,
                                                   unsigned long long b,
                                                   unsigned long long c) {
    unsigned long long d;
    asm("fma.rn.f32x2 %0, %1, %2, %3;" : "=l"(d) : "l"(a), "l"(b), "l"(c));
    return d;
}

#define WQ(k) wp[(k) < 6 ? (k) : 10 - (k)]

__global__ void __launch_bounds__(NT, 3)
ssim_main(const float *__restrict__ img1, const float *__restrict__ img2,
          float *__restrict__ out) {
    extern __shared__ ulonglong2 s_v[];          // [TY][SVW] v-conv results
    __shared__ float s_red[NT / 32];

    const int tid = threadIdx.x;
    const size_t base = (size_t)blockIdx.z * (IMG_H * IMG_W);
    const int x0 = blockIdx.x * TX;              // output col origin
    const int y0 = blockIdx.y * TY;              // output row origin

    unsigned long long wp[6];
#pragma unroll
    for (int k = 0; k < 6; k++) wp[k] = pack2(W11_c[k], W11_c[k]);

    // ============ Phase A: vertical conv, global -> regs -> smem ==========
    // thread = (col 0..41, strip 0..5); lanes walk consecutive cols ->
    // coalesced LDG. 9 outputs x 2 packed accumulators = 18 fma chains.
    if (tid < VCOLS * NSTRIPS) {
        const int col = tid % VCOLS;
        const int s   = tid / VCOLS;
        const int gx  = x0 + col - 5;
        const bool xok = (unsigned)gx < (unsigned)IMG_W;
        const int ry0 = s * RSTRIP;

        unsigned long long amu[RSTRIP], ase[RSTRIP];
#pragma unroll
        for (int o = 0; o < RSTRIP; o++) { amu[o] = 0ULL; ase[o] = 0ULL; }

#pragma unroll
        for (int jj = 0; jj < RSTRIP + 10; jj++) {
            const int gy = y0 + ry0 + jj - 5;
            float a = 0.0f, b = 0.0f;
            if (xok && (unsigned)gy < (unsigned)IMG_H) {
                const size_t off = base + (size_t)gy * IMG_W + gx;
                a = img1[off];
                b = img2[off];
            }
            const unsigned long long v  = pack2(a, b);
            const unsigned long long sp = pack2(fmaf(a, a, b * b), a * b);
#pragma unroll
            for (int o = 0; o < RSTRIP; o++) {
                const int k = jj - o;
                if (k >= 0 && k < 11) {
                    amu[o] = fma2(WQ(k), v,  amu[o]);
                    ase[o] = fma2(WQ(k), sp, ase[o]);
                }
            }
        }
#pragma unroll
        for (int o = 0; o < RSTRIP; o++)
            s_v[(ry0 + o) * SVW + col] = make_ulonglong2(amu[o], ase[o]);
    }
    __syncthreads();

    // ============ Phase B: horizontal conv + SSIM =========================
    // thread = (row 0..53, group 0..3 of 8 output cols). Lanes walk rows:
    // stride 43*16B = 172 words = 12 mod 32 -> conflict-free LDS.128.
    float tsum = 0.0f;
    if (tid < TY * 4) {
        const int r  = tid % TY;
        const int g  = tid / TY;
        const int c0 = g * 8;
        const ulonglong2 *pv = s_v + r * SVW + c0;

        unsigned long long amu[8], ase[8];
#pragma unroll
        for (int o = 0; o < 8; o++) { amu[o] = 0ULL; ase[o] = 0ULL; }
#pragma unroll
        for (int j = 0; j < 18; j++) {
            const ulonglong2 v = pv[j];
#pragma unroll
            for (int o = 0; o < 8; o++) {
                const int k = j - o;
                if (k >= 0 && k < 11) {
                    amu[o] = fma2(WQ(k), v.x, amu[o]);
                    ase[o] = fma2(WQ(k), v.y, ase[o]);
                }
            }
        }
        if (y0 + r < IMG_H) {                    // last y-tile predication
            const float C1 = 1e-4f;
            const float C2 = 9e-4f;
#pragma unroll
            for (int o = 0; o < 8; o++) {
                float mu1, mu2, ess, e12;
                unpack2(amu[o], mu1, mu2);
                unpack2(ase[o], ess, e12);
                const float m12 = mu1 * mu2;
                const float m11 = mu1 * mu1;
                const float m22 = mu2 * mu2;
                const float s12 = e12 - m12;
                const float num = (2.0f * m12 + C1) * (2.0f * s12 + C2);
                const float den = (m11 + m22 + C1) * (ess - m11 - m22 + C2);
                tsum += __fdividef(num, den);
            }
        }
    }

    // ============ deterministic reduction =================================
#pragma unroll
    for (int off = 16; off > 0; off >>= 1)
        tsum += __shfl_down_sync(0xffffffffu, tsum, off);
    if ((tid & 31) == 0) s_red[tid >> 5] = tsum;
    __syncthreads();
    if (tid == 0) {
        double bs = 0.0;
#pragma unroll
        for (int i = 0; i < NT / 32; i++) bs += (double)s_red[i];
        const unsigned long long q =
            (unsigned long long)__double2ll_rn(bs * FXSCALE);
        atomicAdd(&g_acc, q);
        __threadfence();
        const unsigned int done = atomicAdd(&g_cnt, 1u);
        if (done == NBLOCKS - 1) {
            const unsigned long long tot = atomicAdd(&g_acc, 0ULL);
            const double mean = ((double)(long long)tot / FXSCALE) / NPIX;
            out[0] = (float)(1.0 - mean);
            g_acc = 0ULL;        // reset for next graph replay
            g_cnt = 0u;
            __threadfence();
        }
    }
}

extern "C" void kernel_launch(void *const *d_in, const int *in_sizes, int n_in,
                              void *d_out, int out_size) {
    (void)in_sizes; (void)n_in; (void)out_size;
    const float *img1 = (const float *)d_in[0];
    const float *img2 = (const float *)d_in[1];
    float *out = (float *)d_out;

    static const int SMEM_BYTES = (int)(TY * SVW * sizeof(ulonglong2)); // 37152
    cudaFuncSetAttribute(ssim_main, cudaFuncAttributeMaxDynamicSharedMemorySize,
                         SMEM_BYTES);

    dim3 grid(NTILES_X, NTILES_Y, PLANES);
    ssim_main<<<grid, NT, SMEM_BYTES>>>(img1, img2, out);
}

// round 7
// speedup vs baseline: 1.0015x; 1.0015x over previous
#include <cuda_runtime.h>
#include <stdint.h>

// ---------------------------------------------------------------------------
// SSIM loss, (16,3,512,512) fp32. Separable 11x11 Gaussian.
// Phase A: VERTICAL conv first, registers, straight from global (coalesced),
//          42 cols x 54 rows of v-results -> smem (only intermediate).
// Phase B: horizontal conv + SSIM from smem, LDS.128 conflict-free.
// 4 channels packed in ulonglong2: (mu1,mu2)|(Ess,E12) via fma.rn.f32x2.
// Single kernel; order-independent fixed-point atomic reduction.
// ---------------------------------------------------------------------------

#define IMG_H   512
#define IMG_W   512
#define PLANES  48
#define TX      32
#define TY      54
#define RSTRIP  9             // v-conv output rows per Phase-A thread
#define NSTRIPS 6             // 6*9 = 54
#define VCOLS   42            // TX + 10 columns of v-results
#define SVW     43            // ulonglong2 row stride (42 + 1 pad)
#define NT      256
#define NTILES_X 16
#define NTILES_Y 10           // 10*54 = 540 >= 512 (last tile predicated)
#define NBLOCKS (NTILES_X * NTILES_Y * PLANES)   // 7680
#define NPIX    12582912.0
#define FXSCALE 2147483648.0

__device__ __constant__ const float W11_c[11] = {
    0.00102838f, 0.00759876f, 0.03600077f, 0.10936071f, 0.21300554f,
    0.26601172f,
    0.21300554f, 0.10936071f, 0.03600077f, 0.00759876f, 0.00102838f
};

__device__ unsigned long long g_acc;   // zero at load; finalizer resets
__device__ unsigned int       g_cnt;

__device__ __forceinline__ unsigned long long pack2(float lo, float hi) {
    unsigned long long r;
    asm("mov.b64 %0, {%1, %2};" : "=l"(r) : "f"(lo), "f"(hi));
    return r;
}
__device__ __forceinline__ void unpack2(unsigned long long v, float &lo, float &hi) {
    asm("mov.b64 {%0, %1}, %2;" : "=f"(lo), "=f"(hi) : "l"(v));
}
__device__ __forceinline__ unsigned long long fma2(unsigned long long a,
                                                   unsigned long long b,
                                                   unsigned long long c) {
    unsigned long long d;
    asm("fma.rn.f32x2 %0, %1, %2, %3;" : "=l"(d) : "l"(a), "l"(b), "l"(c));
    return d;
}

#define WQ(k) wp[(k) < 6 ? (k) : 10 - (k)]

__global__ void __launch_bounds__(NT, 3)
ssim_main(const float *__restrict__ img1, const float *__restrict__ img2,
          float *__restrict__ out) {
    extern __shared__ ulonglong2 s_v[];          // [TY][SVW] v-conv results
    __shared__ float s_red[NT / 32];

    const int tid = threadIdx.x;
    const size_t base = (size_t)blockIdx.z * (IMG_H * IMG_W);
    const int x0 = blockIdx.x * TX;              // output col origin
    const int y0 = blockIdx.y * TY;              // output row origin

    unsigned long long wp[6];
#pragma unroll
    for (int k = 0; k < 6; k++) wp[k] = pack2(W11_c[k], W11_c[k]);

    // ============ Phase A: vertical conv, global -> regs -> smem ==========
    // thread = (col 0..41, strip 0..5); lanes walk consecutive cols ->
    // coalesced LDG. 9 outputs x 2 packed accumulators = 18 fma chains.
    if (tid < VCOLS * NSTRIPS) {
        const int col = tid % VCOLS;
        const int s   = tid / VCOLS;
        const int gx  = x0 + col - 5;
        const bool xok = (unsigned)gx < (unsigned)IMG_W;
        const int ry0 = s * RSTRIP;

        unsigned long long amu[RSTRIP], ase[RSTRIP];
#pragma unroll
        for (int o = 0; o < RSTRIP; o++) { amu[o] = 0ULL; ase[o] = 0ULL; }

#pragma unroll
        for (int jj = 0; jj < RSTRIP + 10; jj++) {
            const int gy = y0 + ry0 + jj - 5;
            float a = 0.0f, b = 0.0f;
            if (xok && (unsigned)gy < (unsigned)IMG_H) {
                const size_t off = base + (size_t)gy * IMG_W + gx;
                a = img1[off];
                b = img2[off];
            }
            const unsigned long long v  = pack2(a, b);
            const unsigned long long sp = pack2(fmaf(a, a, b * b), a * b);
#pragma unroll
            for (int o = 0; o < RSTRIP; o++) {
                const int k = jj - o;
                if (k >= 0 && k < 11) {
                    amu[o] = fma2(WQ(k), v,  amu[o]);
                    ase[o] = fma2(WQ(k), sp, ase[o]);
                }
            }
        }
#pragma unroll
        for (int o = 0; o < RSTRIP; o++)
            s_v[(ry0 + o) * SVW + col] = make_ulonglong2(amu[o], ase[o]);
    }
    __syncthreads();

    // ============ Phase B: horizontal conv + SSIM =========================
    // thread = (row 0..53, group 0..3 of 8 output cols). Lanes walk rows:
    // stride 43*16B = 172 words = 12 mod 32 -> conflict-free LDS.128.
    float tsum = 0.0f;
    if (tid < TY * 4) {
        const int r  = tid % TY;
        const int g  = tid / TY;
        const int c0 = g * 8;
        const ulonglong2 *pv = s_v + r * SVW + c0;

        unsigned long long amu[8], ase[8];
#pragma unroll
        for (int o = 0; o < 8; o++) { amu[o] = 0ULL; ase[o] = 0ULL; }
#pragma unroll
        for (int j = 0; j < 18; j++) {
            const ulonglong2 v = pv[j];
#pragma unroll
            for (int o = 0; o < 8; o++) {
                const int k = j - o;
                if (k >= 0 && k < 11) {
                    amu[o] = fma2(WQ(k), v.x, amu[o]);
                    ase[o] = fma2(WQ(k), v.y, ase[o]);
                }
            }
        }
        if (y0 + r < IMG_H) {                    // last y-tile predication
            const float C1 = 1e-4f;
            const float C2 = 9e-4f;
#pragma unroll
            for (int o = 0; o < 8; o++) {
                float mu1, mu2, ess, e12;
                unpack2(amu[o], mu1, mu2);
                unpack2(ase[o], ess, e12);
                const float m12 = mu1 * mu2;
                const float m11 = mu1 * mu1;
                const float m22 = mu2 * mu2;
                const float s12 = e12 - m12;
                const float num = (2.0f * m12 + C1) * (2.0f * s12 + C2);
                const float den = (m11 + m22 + C1) * (ess - m11 - m22 + C2);
                tsum += __fdividef(num, den);
            }
        }
    }

    // ============ deterministic reduction =================================
#pragma unroll
    for (int off = 16; off > 0; off >>= 1)
        tsum += __shfl_down_sync(0xffffffffu, tsum, off);
    if ((tid & 31) == 0) s_red[tid >> 5] = tsum;
    __syncthreads();
    if (tid == 0) {
        double bs = 0.0;
#pragma unroll
        for (int i = 0; i < NT / 32; i++) bs += (double)s_red[i];
        const unsigned long long q =
            (unsigned long long)__double2ll_rn(bs * FXSCALE);
        atomicAdd(&g_acc, q);
        __threadfence();
        const unsigned int done = atomicAdd(&g_cnt, 1u);
        if (done == NBLOCKS - 1) {
            const unsigned long long tot = atomicAdd(&g_acc, 0ULL);
            const double mean = ((double)(long long)tot / FXSCALE) / NPIX;
            out[0] = (float)(1.0 - mean);
            g_acc = 0ULL;        // reset for next graph replay
            g_cnt = 0u;
            __threadfence();
        }
    }
}

extern "C" void kernel_launch(void *const *d_in, const int *in_sizes, int n_in,
                              void *d_out, int out_size) {
    (void)in_sizes; (void)n_in; (void)out_size;
    const float *img1 = (const float *)d_in[0];
    const float *img2 = (const float *)d_in[1];
    float *out = (float *)d_out;

    static const int SMEM_BYTES = (int)(TY * SVW * sizeof(ulonglong2)); // 37152
    cudaFuncSetAttribute(ssim_main, cudaFuncAttributeMaxDynamicSharedMemorySize,
                         SMEM_BYTES);

    dim3 grid(NTILES_X, NTILES_Y, PLANES);
    ssim_main<<<grid, NT, SMEM_BYTES>>>(img1, img2, out);
}